// round 8
// baseline (speedup 1.0000x reference)
#include <cuda_runtime.h>
#include <cstdint>

#define Bn 64
#define Fn 64
#define Cn 8
#define Pn 16384              // pixels per image (128x128)
#define Kn 10                 // steps_to_run
#define BP (Bn * Pn)          // 1048576 total pixels

// Scratch (device globals: allocation-free per harness rules)
// colour is PIXEL-MAJOR: g_colour[((b*Pn)+p)*Cn + c]  (33.5 MB)
__device__ float g_colour[(size_t)Bn * Pn * Cn];
__device__ float g_stage[(size_t)(Kn - 1) * BP];  // [k][b*p]  37.7 MB (streamed)

// ---------------------------------------------------------------------------
__device__ __forceinline__ uint32_t smem_u32(const void* p) {
    uint32_t a;
    asm("{ .reg .u64 t; cvta.to.shared.u64 t, %1; cvt.u32.u64 %0, t; }"
        : "=r"(a) : "l"(p));
    return a;
}

// ---------------------------------------------------------------------------
// Kernel 1: 1x1 conv + gate + coord channels -> g_colour (pixel-major).
// ---------------------------------------------------------------------------
__global__ void conv_kernel(const float4* __restrict__ feat,
                            const float* __restrict__ w,
                            const float* __restrict__ bias,
                            const float* __restrict__ gate) {
    __shared__ float ws[Cn * Fn];
    __shared__ float bs[Cn];
    int tid = threadIdx.x;
    for (int i = tid; i < Cn * Fn; i += blockDim.x) ws[i] = w[i];
    if (tid < Cn) bs[tid] = bias[tid];
    __syncthreads();

    int gidx = blockIdx.x * blockDim.x + tid;   // 0 .. BP/4-1
    int b = gidx >> 12;
    int q = gidx & 4095;

    const float4* fb = feat + (size_t)b * (Fn * Pn / 4) + q;

    float4 acc[Cn];
#pragma unroll
    for (int c = 0; c < Cn; c++) {
        float bb = bs[c];
        acc[c] = make_float4(bb, bb, bb, bb);
    }

#pragma unroll 8
    for (int f = 0; f < Fn; f++) {
        float4 v = __ldcs(&fb[(size_t)f * (Pn / 4)]);   // stream features
#pragma unroll
        for (int c = 0; c < Cn; c++) {
            float wc = ws[c * Fn + f];
            acc[c].x += v.x * wc;
            acc[c].y += v.y * wc;
            acc[c].z += v.z * wc;
            acc[c].w += v.w * wc;
        }
    }

    float g = gate[0];
#pragma unroll
    for (int c = 0; c < Cn; c++) {
        acc[c].x *= g; acc[c].y *= g; acc[c].z *= g; acc[c].w *= g;
    }

    int p0 = q << 2;
    int h  = p0 >> 7;
    int wc0 = p0 & 127;
    const float step = 2.0f / 127.0f;
    float yy = -1.0f + step * (float)h;
    acc[6].x += yy; acc[6].y += yy; acc[6].z += yy; acc[6].w += yy;
    float xx = -1.0f + step * (float)wc0;
    acc[7].x += xx;
    acc[7].y += xx + step;
    acc[7].z += xx + 2.0f * step;
    acc[7].w += xx + 3.0f * step;

    // transpose in-register -> pixel-major store (8 float4 = 128B contiguous)
    float4* cb = (float4*)g_colour;
    size_t base = ((size_t)b * Pn + (size_t)p0) * 2;
    cb[base + 0] = make_float4(acc[0].x, acc[1].x, acc[2].x, acc[3].x);
    cb[base + 1] = make_float4(acc[4].x, acc[5].x, acc[6].x, acc[7].x);
    cb[base + 2] = make_float4(acc[0].y, acc[1].y, acc[2].y, acc[3].y);
    cb[base + 3] = make_float4(acc[4].y, acc[5].y, acc[6].y, acc[7].y);
    cb[base + 4] = make_float4(acc[0].z, acc[1].z, acc[2].z, acc[3].z);
    cb[base + 5] = make_float4(acc[4].z, acc[5].z, acc[6].z, acc[7].z);
    cb[base + 6] = make_float4(acc[0].w, acc[1].w, acc[2].w, acc[3].w);
    cb[base + 7] = make_float4(acc[4].w, acc[5].w, acc[6].w, acc[7].w);
}

// ---------------------------------------------------------------------------
// Kernel 2: persistent step loop. 128 CTAs x 512 thr, cluster(2): one batch
// per cluster, each CTA owns half the image (8192 px = 16 px/thread).
// Colour is pixel-major: each thread re-reads ITS OWN 512B every step -> L1.
// ---------------------------------------------------------------------------
__global__ void __launch_bounds__(512, 1) __cluster_dims__(2, 1, 1)
step_loop_kernel(float* __restrict__ out, const float4* __restrict__ rp4,
                 const float* __restrict__ log_sigma) {
    __shared__ float s_wv[16];
    __shared__ int   s_wp[16];
    __shared__ float s_slotv[2];
    __shared__ int   s_sloti[2];
    __shared__ int   s_pstar;
    __shared__ float4 s_seedv[2];

    const int tid = threadIdx.x;
    const int b = blockIdx.x >> 1;              // batch
    const int h = blockIdx.x & 1;               // half of image
    uint32_t rank;
    asm("mov.u32 %0, %%cluster_ctarank;" : "=r"(rank));
    const uint32_t peer = rank ^ 1u;

    const float invsig = expf(-log_sigma[0]);
    const float LOG2E = 1.4426950408889634f;
    const float L_LO  = -4.6051702f;      // log(0.01f)
    const float L_HI  = -0.010050326f;    // log(0.99f)

    const int base4 = h * 2048 + tid;           // float4 index in plane (stage/rp)
    const float4* colour4 = (const float4*)g_colour;
    float4* stage4 = (float4*)g_stage;

    float4 rp[4];
#pragma unroll
    for (int j = 0; j < 4; j++)
        rp[j] = __ldg(&rp4[b * 4096 + base4 + j * 512]);

    float ls[16];
#pragma unroll
    for (int i = 0; i < 16; i++) ls[i] = 0.0f;
    float lm9[16];

    // k=0 argmax candidate straight from rand_pixel (scope == 1)
    float vl = -3.402823466e38f; int pl = 0;
#pragma unroll
    for (int j = 0; j < 4; j++) {
        int pbase = h * 8192 + j * 2048 + (tid << 2);
        float vv[4] = {rp[j].x, rp[j].y, rp[j].z, rp[j].w};
#pragma unroll
        for (int i = 0; i < 4; i++)
            if (vv[i] > vl) { vl = vv[i]; pl = pbase + i; }   // ascending p: keep first
    }

    for (int k = 0; k < Kn; k++) {
        // ---- CTA argmax reduce of (vl, pl), first-index tie-break ----
#pragma unroll
        for (int o = 16; o; o >>= 1) {
            float ov = __shfl_down_sync(0xFFFFFFFFu, vl, o);
            int   op = __shfl_down_sync(0xFFFFFFFFu, pl, o);
            if (ov > vl || (ov == vl && op < pl)) { vl = ov; pl = op; }
        }
        if ((tid & 31) == 0) { s_wv[tid >> 5] = vl; s_wp[tid >> 5] = pl; }
        __syncthreads();
        if (tid < 32) {
            float v2 = (tid < 16) ? s_wv[tid] : -3.402823466e38f;
            int   p2 = (tid < 16) ? s_wp[tid] : 0x7FFFFFFF;
#pragma unroll
            for (int o = 8; o; o >>= 1) {
                float ov = __shfl_down_sync(0xFFFFFFFFu, v2, o);
                int   op = __shfl_down_sync(0xFFFFFFFFu, p2, o);
                if (ov > v2 || (ov == v2 && op < p2)) { v2 = ov; p2 = op; }
            }
            if (tid == 0) { s_slotv[k & 1] = v2; s_sloti[k & 1] = p2; }
        }
        __syncthreads();

        // ---- exchange CTA winners across the 2-CTA cluster ----
        asm volatile("barrier.cluster.arrive.aligned;" ::: "memory");
        asm volatile("barrier.cluster.wait.aligned;" ::: "memory");
        if (tid == 0) {
            int par = k & 1;
            uint32_t av = smem_u32(&s_slotv[par]);
            uint32_t ai = smem_u32(&s_sloti[par]);
            float pv; int pi;
            asm volatile("{ .reg .b32 r; mapa.shared::cluster.u32 r, %1, %2; "
                         "ld.shared::cluster.f32 %0, [r]; }"
                         : "=f"(pv) : "r"(av), "r"(peer));
            asm volatile("{ .reg .b32 r; mapa.shared::cluster.u32 r, %1, %2; "
                         "ld.shared::cluster.u32 %0, [r]; }"
                         : "=r"(pi) : "r"(ai), "r"(peer));
            float mv = s_slotv[par]; int mp = s_sloti[par];
            if (pv > mv || (pv == mv && pi < mp)) mp = pi;
            s_pstar = mp;
        }
        __syncthreads();
        if (tid < 2)
            s_seedv[tid] = colour4[((size_t)b * Pn + (size_t)s_pstar) * 2 + tid];
        __syncthreads();

        float4 s0 = s_seedv[0];
        float4 s1 = s_seedv[1];

        const int last = (k == Kn - 1);
        vl = -3.402823466e38f; pl = 0;

        // ---- pixel loop: 16 px/thread, pixel-major colour (L1-resident) ----
#pragma unroll
        for (int j = 0; j < 4; j++) {
            int pbase = h * 8192 + j * 2048 + (tid << 2);
            const float4* cp = colour4 + ((size_t)b * Pn + (size_t)pbase) * 2;

            float4 ca[4], cbv[4];
#pragma unroll
            for (int i = 0; i < 4; i++) {
                ca[i]  = __ldg(&cp[2 * i]);        // ch 0-3
                cbv[i] = __ldg(&cp[2 * i + 1]);    // ch 4-7
            }

            float dd[4];
#pragma unroll
            for (int i = 0; i < 4; i++) {
                float tx = ca[i].x - s0.x;
                float ty = ca[i].y - s0.y;
                float tz = ca[i].z - s0.z;
                float tw = ca[i].w - s0.w;
                float d2 = tx * tx + ty * ty + tz * tz + tw * tw;
                tx = cbv[i].x - s1.x; d2 += tx * tx;
                ty = cbv[i].y - s1.y; d2 += ty * ty;
                tz = cbv[i].z - s1.z; d2 += tz * tz;
                tw = cbv[i].w - s1.w; d2 += tw * tw;
                dd[i] = d2;
            }

            float rr[4] = {rp[j].x, rp[j].y, rp[j].z, rp[j].w};
            float lmv[4];
#pragma unroll
            for (int i = 0; i < 4; i++) {
                float t = -(dd[i] * invsig);
                float alpha = exp2f(t * LOG2E);
                alpha = fminf(fmaxf(alpha, 0.01f), 0.99f);
                float log_a = fminf(fmaxf(t, L_LO), L_HI);
                int li = j * 4 + i;
                float lsv = ls[li];
                lmv[i] = lsv + log_a;
                lsv += logf(1.0f - alpha);
                ls[li] = lsv;
                if (!last) {
                    float v = rr[i] * expf(lsv);
                    if (v > vl) { vl = v; pl = pbase + i; }   // ascending p
                } else {
                    lm9[li] = lmv[i];
                }
            }
            if (!last) {
                float4 lm4 = make_float4(lmv[0], lmv[1], lmv[2], lmv[3]);
                __stcs(&stage4[(size_t)k * (BP / 4) + b * 4096 + base4 + j * 512], lm4);
            }
        }
    }

    // ---- epilogue: assemble [b,p,11] output, contiguous 44B per pixel ----
#pragma unroll
    for (int j = 0; j < 4; j++) {
        int pbase = h * 8192 + j * 2048 + (tid << 2);
        float* op0 = out + ((size_t)b * Pn + pbase) * (Kn + 1);
        float* op1 = op0 + (Kn + 1);
        float* op2 = op1 + (Kn + 1);
        float* op3 = op2 + (Kn + 1);
#pragma unroll
        for (int kk = 0; kk < Kn - 1; kk++) {
            float4 s = __ldcs(&stage4[(size_t)kk * (BP / 4) + b * 4096 + base4 + j * 512]);
            __stcs(op0 + kk, s.x);
            __stcs(op1 + kk, s.y);
            __stcs(op2 + kk, s.z);
            __stcs(op3 + kk, s.w);
        }
        __stcs(op0 + Kn - 1, lm9[j * 4 + 0]); __stcs(op0 + Kn, ls[j * 4 + 0]);
        __stcs(op1 + Kn - 1, lm9[j * 4 + 1]); __stcs(op1 + Kn, ls[j * 4 + 1]);
        __stcs(op2 + Kn - 1, lm9[j * 4 + 2]); __stcs(op2 + Kn, ls[j * 4 + 2]);
        __stcs(op3 + Kn - 1, lm9[j * 4 + 3]); __stcs(op3 + Kn, ls[j * 4 + 3]);
    }
}

// ---------------------------------------------------------------------------
extern "C" void kernel_launch(void* const* d_in, const int* in_sizes, int n_in,
                              void* d_out, int out_size) {
    const float* features  = (const float*)d_in[0];
    const float* rand_pix  = (const float*)d_in[1];
    const float* conv_w    = (const float*)d_in[2];
    const float* conv_b    = (const float*)d_in[3];
    const float* gate      = (const float*)d_in[4];
    const float* log_sigma = (const float*)d_in[5];
    float* out = (float*)d_out;

    (void)in_sizes; (void)n_in; (void)out_size;

    conv_kernel<<<(BP / 4) / 256, 256>>>((const float4*)features,
                                         conv_w, conv_b, gate);
    step_loop_kernel<<<128, 512>>>(out, (const float4*)rand_pix, log_sigma);
}

// round 9
// speedup vs baseline: 1.3910x; 1.3910x over previous
#include <cuda_runtime.h>
#include <cstdint>

#define Bn 64
#define Fn 64
#define Cn 8
#define Pn 16384              // pixels per image (128x128)
#define Kn 10                 // steps_to_run
#define BP (Bn * Pn)          // 1048576 total pixels
#define CPX 4096              // pixels per CTA (cluster of 4)
#define THR 512               // threads per CTA
#define PXT 8                 // pixels per thread
#define DSMEM_BYTES (2 * CPX * 16)   // 131072: two float4 planes

// Scratch (device globals: allocation-free per harness rules)
// colour is PIXEL-MAJOR: g_colour[((b*Pn)+p)*Cn + c]  (33.5 MB)
__device__ float g_colour[(size_t)Bn * Pn * Cn];
__device__ float g_stage[(size_t)(Kn - 1) * BP];  // [k][b*p]  37.7 MB (streamed)

// ---------------------------------------------------------------------------
__device__ __forceinline__ uint32_t smem_u32(const void* p) {
    uint32_t a;
    asm("{ .reg .u64 t; cvta.to.shared.u64 t, %1; cvt.u32.u64 %0, t; }"
        : "=r"(a) : "l"(p));
    return a;
}
__device__ __forceinline__ float ld_dsmem_f32(uint32_t saddr, uint32_t rank) {
    float v;
    asm volatile("{ .reg .b32 r; mapa.shared::cluster.u32 r, %1, %2; "
                 "ld.shared::cluster.f32 %0, [r]; }"
                 : "=f"(v) : "r"(saddr), "r"(rank));
    return v;
}
__device__ __forceinline__ int ld_dsmem_s32(uint32_t saddr, uint32_t rank) {
    int v;
    asm volatile("{ .reg .b32 r; mapa.shared::cluster.u32 r, %1, %2; "
                 "ld.shared::cluster.u32 %0, [r]; }"
                 : "=r"(v) : "r"(saddr), "r"(rank));
    return v;
}

// ---------------------------------------------------------------------------
// Kernel 1: 1x1 conv + gate + coord channels -> g_colour (pixel-major).
// ---------------------------------------------------------------------------
__global__ void conv_kernel(const float4* __restrict__ feat,
                            const float* __restrict__ w,
                            const float* __restrict__ bias,
                            const float* __restrict__ gate) {
    __shared__ float ws[Cn * Fn];
    __shared__ float bs[Cn];
    int tid = threadIdx.x;
    for (int i = tid; i < Cn * Fn; i += blockDim.x) ws[i] = w[i];
    if (tid < Cn) bs[tid] = bias[tid];
    __syncthreads();

    int gidx = blockIdx.x * blockDim.x + tid;   // 0 .. BP/4-1
    int b = gidx >> 12;
    int q = gidx & 4095;

    const float4* fb = feat + (size_t)b * (Fn * Pn / 4) + q;

    float4 acc[Cn];
#pragma unroll
    for (int c = 0; c < Cn; c++) {
        float bb = bs[c];
        acc[c] = make_float4(bb, bb, bb, bb);
    }

#pragma unroll 8
    for (int f = 0; f < Fn; f++) {
        float4 v = __ldcs(&fb[(size_t)f * (Pn / 4)]);   // stream features
#pragma unroll
        for (int c = 0; c < Cn; c++) {
            float wc = ws[c * Fn + f];
            acc[c].x += v.x * wc;
            acc[c].y += v.y * wc;
            acc[c].z += v.z * wc;
            acc[c].w += v.w * wc;
        }
    }

    float g = gate[0];
#pragma unroll
    for (int c = 0; c < Cn; c++) {
        acc[c].x *= g; acc[c].y *= g; acc[c].z *= g; acc[c].w *= g;
    }

    int p0 = q << 2;
    int h  = p0 >> 7;
    int wc0 = p0 & 127;
    const float step = 2.0f / 127.0f;
    float yy = -1.0f + step * (float)h;
    acc[6].x += yy; acc[6].y += yy; acc[6].z += yy; acc[6].w += yy;
    float xx = -1.0f + step * (float)wc0;
    acc[7].x += xx;
    acc[7].y += xx + step;
    acc[7].z += xx + 2.0f * step;
    acc[7].w += xx + 3.0f * step;

    // transpose in-register -> pixel-major store (8 float4 = 128B contiguous)
    float4* cb = (float4*)g_colour;
    size_t base = ((size_t)b * Pn + (size_t)p0) * 2;
    cb[base + 0] = make_float4(acc[0].x, acc[1].x, acc[2].x, acc[3].x);
    cb[base + 1] = make_float4(acc[4].x, acc[5].x, acc[6].x, acc[7].x);
    cb[base + 2] = make_float4(acc[0].y, acc[1].y, acc[2].y, acc[3].y);
    cb[base + 3] = make_float4(acc[4].y, acc[5].y, acc[6].y, acc[7].y);
    cb[base + 4] = make_float4(acc[0].z, acc[1].z, acc[2].z, acc[3].z);
    cb[base + 5] = make_float4(acc[4].z, acc[5].z, acc[6].z, acc[7].z);
    cb[base + 6] = make_float4(acc[0].w, acc[1].w, acc[2].w, acc[3].w);
    cb[base + 7] = make_float4(acc[4].w, acc[5].w, acc[6].w, acc[7].w);
}

// ---------------------------------------------------------------------------
// Kernel 2: persistent step loop, cluster(4) = one batch. 256 CTAs x 512 thr.
// Each CTA holds its 4096-pixel colour slice in SMEM as two float4 planes.
// Per step: CTA argmax reduce -> cluster barrier -> DSMEM slot merge ->
// DSMEM seed gather -> SMEM pixel loop. rp/log_s/last masks in registers.
// ---------------------------------------------------------------------------
__global__ void __launch_bounds__(THR, 1) __cluster_dims__(4, 1, 1)
step_loop_kernel(float* __restrict__ out, const float* __restrict__ rpf,
                 const float* __restrict__ log_sigma) {
    extern __shared__ float4 dynsm[];
    float4* sA = dynsm;            // ch 0-3, [CPX]
    float4* sB = dynsm + CPX;      // ch 4-7, [CPX]

    __shared__ float s_wv[16];
    __shared__ int   s_wp[16];
    __shared__ float s_slotv[2];
    __shared__ int   s_sloti[2];
    __shared__ float s_seed[Cn];

    const int tid = threadIdx.x;
    const int b = blockIdx.x >> 2;              // batch (cluster id)
    uint32_t rank;
    asm("mov.u32 %0, %%cluster_ctarank;" : "=r"(rank));

    const size_t bPn = (size_t)b * Pn;
    const int ctaPx = (int)rank * CPX;

    const float invsig = expf(-log_sigma[0]);
    const float LOG2E = 1.4426950408889634f;
    const float L_LO  = -4.6051702f;      // log(0.01f)
    const float L_HI  = -0.010050326f;    // log(0.99f)

    // ---- load colour slice into SMEM (split planes, coalesced) ----
    const float4* colour4 = (const float4*)g_colour;
    size_t cbase = (bPn + (size_t)ctaPx) * 2;
#pragma unroll
    for (int j = 0; j < 16; j++) {
        int idx = j * THR + tid;            // 0..8191
        float4 f = colour4[cbase + idx];
        int px = idx >> 1;
        if (idx & 1) sB[px] = f; else sA[px] = f;
    }
    __syncthreads();
    // colour must be visible cluster-wide before any DSMEM seed gather
    asm volatile("barrier.cluster.arrive.aligned;" ::: "memory");
    asm volatile("barrier.cluster.wait.aligned;" ::: "memory");

    // ---- per-thread state ----
    float rp[PXT], ls[PXT], lm9[PXT];
#pragma unroll
    for (int i = 0; i < PXT; i++) {
        rp[i] = __ldg(&rpf[bPn + ctaPx + i * THR + tid]);
        ls[i] = 0.0f;
    }

    // k=0 argmax candidate straight from rand_pixel (scope == 1)
    float vl = -3.402823466e38f; int pl = 0;
#pragma unroll
    for (int i = 0; i < PXT; i++) {
        int gp = ctaPx + i * THR + tid;     // ascending in i
        if (rp[i] > vl) { vl = rp[i]; pl = gp; }
    }

    for (int k = 0; k < Kn; k++) {
        // ---- CTA argmax reduce of (vl, pl), first-index tie-break ----
#pragma unroll
        for (int o = 16; o; o >>= 1) {
            float ov = __shfl_down_sync(0xFFFFFFFFu, vl, o);
            int   op = __shfl_down_sync(0xFFFFFFFFu, pl, o);
            if (ov > vl || (ov == vl && op < pl)) { vl = ov; pl = op; }
        }
        if ((tid & 31) == 0) { s_wv[tid >> 5] = vl; s_wp[tid >> 5] = pl; }
        __syncthreads();
        if (tid < 32) {
            float v2 = (tid < 16) ? s_wv[tid] : -3.402823466e38f;
            int   p2 = (tid < 16) ? s_wp[tid] : 0x7FFFFFFF;
#pragma unroll
            for (int o = 8; o; o >>= 1) {
                float ov = __shfl_down_sync(0xFFFFFFFFu, v2, o);
                int   op = __shfl_down_sync(0xFFFFFFFFu, p2, o);
                if (ov > v2 || (ov == v2 && op < p2)) { v2 = ov; p2 = op; }
            }
            if (tid == 0) { s_slotv[k & 1] = v2; s_sloti[k & 1] = p2; }
        }
        __syncthreads();

        // ---- exchange CTA winners across the 4-CTA cluster ----
        asm volatile("barrier.cluster.arrive.aligned;" ::: "memory");
        asm volatile("barrier.cluster.wait.aligned;" ::: "memory");

        if (tid < 32) {
            int bp = 0;
            if (tid == 0) {
                int par = k & 1;
                float bv = s_slotv[par];
                bp = s_sloti[par];
                uint32_t av = smem_u32(&s_slotv[par]);
                uint32_t ai = smem_u32(&s_sloti[par]);
#pragma unroll
                for (uint32_t r = 0; r < 4; r++) {
                    if (r == rank) continue;
                    float pv = ld_dsmem_f32(av, r);
                    int   pi = ld_dsmem_s32(ai, r);
                    if (pv > bv || (pv == bv && pi < bp)) { bv = pv; bp = pi; }
                }
            }
            bp = __shfl_sync(0xFFFFFFFFu, bp, 0);
            // seed gather from the owner CTA's SMEM via DSMEM
            if (tid < Cn) {
                uint32_t owner = (uint32_t)bp >> 12;
                int lpx = bp & (CPX - 1);
                uint32_t addr = (tid < 4)
                    ? smem_u32(&sA[lpx]) + (uint32_t)(tid & 3) * 4u
                    : smem_u32(&sB[lpx]) + (uint32_t)(tid & 3) * 4u;
                s_seed[tid] = ld_dsmem_f32(addr, owner);
            }
        }
        __syncthreads();

        float s0x = s_seed[0], s0y = s_seed[1], s0z = s_seed[2], s0w = s_seed[3];
        float s1x = s_seed[4], s1y = s_seed[5], s1z = s_seed[6], s1w = s_seed[7];

        const int last = (k == Kn - 1);
        vl = -3.402823466e38f; pl = 0;

        // ---- pixel loop: 8 px/thread from SMEM (conflict-free LDS.128) ----
#pragma unroll
        for (int i = 0; i < PXT; i++) {
            int lp = i * THR + tid;
            float4 ca = sA[lp];
            float4 cb = sB[lp];

            float tx = ca.x - s0x;
            float ty = ca.y - s0y;
            float tz = ca.z - s0z;
            float tw = ca.w - s0w;
            float d2 = tx * tx + ty * ty + tz * tz + tw * tw;
            tx = cb.x - s1x; d2 += tx * tx;
            ty = cb.y - s1y; d2 += ty * ty;
            tz = cb.z - s1z; d2 += tz * tz;
            tw = cb.w - s1w; d2 += tw * tw;

            float t = -(d2 * invsig);
            float alpha = exp2f(t * LOG2E);
            alpha = fminf(fmaxf(alpha, 0.01f), 0.99f);
            float log_a = fminf(fmaxf(t, L_LO), L_HI);
            float lsv = ls[i];
            float lm = lsv + log_a;
            lsv += logf(1.0f - alpha);
            ls[i] = lsv;

            int gp = ctaPx + lp;
            if (!last) {
                __stcs(&g_stage[(size_t)k * BP + bPn + gp], lm);
                float v = rp[i] * expf(lsv);
                if (v > vl) { vl = v; pl = gp; }     // ascending gp in i
            } else {
                lm9[i] = lm;
            }
        }
    }

    // ---- epilogue: assemble [b,p,11] output ----
#pragma unroll
    for (int i = 0; i < PXT; i++) {
        int gp = ctaPx + i * THR + tid;
        float* op = out + (bPn + gp) * (size_t)(Kn + 1);
#pragma unroll
        for (int kk = 0; kk < Kn - 1; kk++)
            __stcs(&op[kk], __ldcs(&g_stage[(size_t)kk * BP + bPn + gp]));
        __stcs(&op[Kn - 1], lm9[i]);
        __stcs(&op[Kn], ls[i]);
    }
}

// ---------------------------------------------------------------------------
extern "C" void kernel_launch(void* const* d_in, const int* in_sizes, int n_in,
                              void* d_out, int out_size) {
    const float* features  = (const float*)d_in[0];
    const float* rand_pix  = (const float*)d_in[1];
    const float* conv_w    = (const float*)d_in[2];
    const float* conv_b    = (const float*)d_in[3];
    const float* gate      = (const float*)d_in[4];
    const float* log_sigma = (const float*)d_in[5];
    float* out = (float*)d_out;

    (void)in_sizes; (void)n_in; (void)out_size;

    cudaFuncSetAttribute(step_loop_kernel,
                         cudaFuncAttributeMaxDynamicSharedMemorySize,
                         DSMEM_BYTES);

    conv_kernel<<<(BP / 4) / 256, 256>>>((const float4*)features,
                                         conv_w, conv_b, gate);
    step_loop_kernel<<<Bn * 4, THR, DSMEM_BYTES>>>(out, rand_pix, log_sigma);
}

// round 10
// speedup vs baseline: 1.4141x; 1.0166x over previous
#include <cuda_runtime.h>
#include <cstdint>

#define Bn 64
#define Fn 64
#define Cn 8
#define Pn 16384              // pixels per image (128x128)
#define Kn 10                 // steps_to_run
#define BP (Bn * Pn)          // 1048576 total pixels
#define THR 256               // threads per CTA
#define QF4 1024              // float4s per CTA quarter (4096 px)

// Scratch (device globals: allocation-free per harness rules)
// colour is CHANNEL-MAJOR: g_colour[((b*Cn)+c)*Pn + p]  (33.5 MB)
__device__ float g_colour[(size_t)Bn * Cn * Pn];
__device__ float g_stage[(size_t)(Kn - 1) * BP];  // [k][b*p]  37.7 MB (streamed)

// ---------------------------------------------------------------------------
__device__ __forceinline__ uint32_t smem_u32(const void* p) {
    uint32_t a;
    asm("{ .reg .u64 t; cvta.to.shared.u64 t, %1; cvt.u32.u64 %0, t; }"
        : "=r"(a) : "l"(p));
    return a;
}
__device__ __forceinline__ float ld_dsmem_f32(uint32_t saddr, uint32_t rank) {
    float v;
    asm volatile("{ .reg .b32 r; mapa.shared::cluster.u32 r, %1, %2; "
                 "ld.shared::cluster.f32 %0, [r]; }"
                 : "=f"(v) : "r"(saddr), "r"(rank));
    return v;
}
__device__ __forceinline__ int ld_dsmem_s32(uint32_t saddr, uint32_t rank) {
    int v;
    asm volatile("{ .reg .b32 r; mapa.shared::cluster.u32 r, %1, %2; "
                 "ld.shared::cluster.u32 %0, [r]; }"
                 : "=r"(v) : "r"(saddr), "r"(rank));
    return v;
}

// ---------------------------------------------------------------------------
// Kernel 1: 1x1 conv + gate + coord channels -> g_colour (channel-major).
// ---------------------------------------------------------------------------
__global__ void conv_kernel(const float4* __restrict__ feat,
                            const float* __restrict__ w,
                            const float* __restrict__ bias,
                            const float* __restrict__ gate) {
    __shared__ float ws[Cn * Fn];
    __shared__ float bs[Cn];
    int tid = threadIdx.x;
    for (int i = tid; i < Cn * Fn; i += blockDim.x) ws[i] = w[i];
    if (tid < Cn) bs[tid] = bias[tid];
    __syncthreads();

    int gidx = blockIdx.x * blockDim.x + tid;   // 0 .. BP/4-1
    int b = gidx >> 12;
    int q = gidx & 4095;

    const float4* fb = feat + (size_t)b * (Fn * Pn / 4) + q;

    float4 acc[Cn];
#pragma unroll
    for (int c = 0; c < Cn; c++) {
        float bb = bs[c];
        acc[c] = make_float4(bb, bb, bb, bb);
    }

#pragma unroll 8
    for (int f = 0; f < Fn; f++) {
        float4 v = __ldcs(&fb[(size_t)f * (Pn / 4)]);   // stream features
#pragma unroll
        for (int c = 0; c < Cn; c++) {
            float wc = ws[c * Fn + f];
            acc[c].x += v.x * wc;
            acc[c].y += v.y * wc;
            acc[c].z += v.z * wc;
            acc[c].w += v.w * wc;
        }
    }

    float g = gate[0];
#pragma unroll
    for (int c = 0; c < Cn; c++) {
        acc[c].x *= g; acc[c].y *= g; acc[c].z *= g; acc[c].w *= g;
    }

    int p0 = q << 2;
    int h  = p0 >> 7;
    int wc0 = p0 & 127;
    const float step = 2.0f / 127.0f;
    float yy = -1.0f + step * (float)h;
    acc[6].x += yy; acc[6].y += yy; acc[6].z += yy; acc[6].w += yy;
    float xx = -1.0f + step * (float)wc0;
    acc[7].x += xx;
    acc[7].y += xx + step;
    acc[7].z += xx + 2.0f * step;
    acc[7].w += xx + 3.0f * step;

    float4* cb = (float4*)g_colour;
#pragma unroll
    for (int c = 0; c < Cn; c++)
        cb[((size_t)b * Cn + c) * (Pn / 4) + q] = acc[c];
}

// ---------------------------------------------------------------------------
// Kernel 2: persistent step loop. 256 CTAs x 256 thr, cluster(4) = one batch.
// Each CTA owns a quarter (4096 px = 16 px/thread). 2 CTAs/SM -> one wave,
// cross-cluster overlap hides per-step sync latency. Colour read from L2.
// ---------------------------------------------------------------------------
__global__ void __launch_bounds__(THR, 2) __cluster_dims__(4, 1, 1)
step_loop_kernel(float* __restrict__ out, const float4* __restrict__ rp4,
                 const float* __restrict__ log_sigma) {
    __shared__ float s_wv[8];
    __shared__ int   s_wp[8];
    __shared__ float s_slotv[2];
    __shared__ int   s_sloti[2];
    __shared__ int   s_pstar;
    __shared__ float s_seed[Cn];

    const int tid = threadIdx.x;
    const int b = blockIdx.x >> 2;              // batch (cluster id)
    uint32_t rank;
    asm("mov.u32 %0, %%cluster_ctarank;" : "=r"(rank));

    const float invsig = expf(-log_sigma[0]);
    const float LOG2E = 1.4426950408889634f;
    const float L_LO  = -4.6051702f;      // log(0.01f)
    const float L_HI  = -0.010050326f;    // log(0.99f)

    const int base4 = (int)rank * QF4 + tid;    // float4 index in batch plane
    const float4* colour4 = (const float4*)g_colour;
    float4* stage4 = (float4*)g_stage;

    float4 rp[4];
#pragma unroll
    for (int j = 0; j < 4; j++)
        rp[j] = __ldg(&rp4[b * 4096 + base4 + j * THR]);

    float ls[16];
#pragma unroll
    for (int i = 0; i < 16; i++) ls[i] = 0.0f;
    float lm9[16];

    // k=0 argmax candidate straight from rand_pixel (scope == 1)
    float vl = -3.402823466e38f; int pl = 0;
#pragma unroll
    for (int j = 0; j < 4; j++) {
        int pbase = (base4 + j * THR) << 2;    // ascending in j
        float vv[4] = {rp[j].x, rp[j].y, rp[j].z, rp[j].w};
#pragma unroll
        for (int i = 0; i < 4; i++)
            if (vv[i] > vl) { vl = vv[i]; pl = pbase + i; }   // keep first idx
    }

    for (int k = 0; k < Kn; k++) {
        // ---- CTA argmax reduce of (vl, pl), first-index tie-break ----
#pragma unroll
        for (int o = 16; o; o >>= 1) {
            float ov = __shfl_down_sync(0xFFFFFFFFu, vl, o);
            int   op = __shfl_down_sync(0xFFFFFFFFu, pl, o);
            if (ov > vl || (ov == vl && op < pl)) { vl = ov; pl = op; }
        }
        if ((tid & 31) == 0) { s_wv[tid >> 5] = vl; s_wp[tid >> 5] = pl; }
        __syncthreads();
        if (tid < 32) {
            float v2 = (tid < 8) ? s_wv[tid] : -3.402823466e38f;
            int   p2 = (tid < 8) ? s_wp[tid] : 0x7FFFFFFF;
#pragma unroll
            for (int o = 4; o; o >>= 1) {
                float ov = __shfl_down_sync(0xFFFFFFFFu, v2, o);
                int   op = __shfl_down_sync(0xFFFFFFFFu, p2, o);
                if (ov > v2 || (ov == v2 && op < p2)) { v2 = ov; p2 = op; }
            }
            if (tid == 0) { s_slotv[k & 1] = v2; s_sloti[k & 1] = p2; }
        }
        __syncthreads();

        // ---- exchange CTA winners across the 4-CTA cluster ----
        asm volatile("barrier.cluster.arrive.aligned;" ::: "memory");
        asm volatile("barrier.cluster.wait.aligned;" ::: "memory");
        if (tid == 0) {
            int par = k & 1;
            float bv = s_slotv[par];
            int   bp = s_sloti[par];
            uint32_t av = smem_u32(&s_slotv[par]);
            uint32_t ai = smem_u32(&s_sloti[par]);
#pragma unroll
            for (uint32_t r = 0; r < 4; r++) {
                if (r == rank) continue;
                float pv = ld_dsmem_f32(av, r);
                int   pi = ld_dsmem_s32(ai, r);
                if (pv > bv || (pv == bv && pi < bp)) { bv = pv; bp = pi; }
            }
            s_pstar = bp;
        }
        __syncthreads();
        if (tid < Cn)
            s_seed[tid] = g_colour[((size_t)b * Cn + tid) * Pn + s_pstar];
        __syncthreads();

        float sd[Cn];
#pragma unroll
        for (int c = 0; c < Cn; c++) sd[c] = s_seed[c];

        const int last = (k == Kn - 1);
        vl = -3.402823466e38f; pl = 0;

        // ---- pixel loop: 16 px/thread, channel-major colour from L2 ----
#pragma unroll
        for (int j = 0; j < 4; j++) {
            int f4 = base4 + j * THR;

            float4 col[Cn];
#pragma unroll
            for (int c = 0; c < Cn; c++)
                col[c] = __ldg(&colour4[((size_t)b * Cn + c) * 4096 + f4]);

            float4 d2 = make_float4(0.f, 0.f, 0.f, 0.f);
#pragma unroll
            for (int c = 0; c < Cn; c++) {
                float sc = sd[c];
                float tx = col[c].x - sc; d2.x += tx * tx;
                float ty = col[c].y - sc; d2.y += ty * ty;
                float tz = col[c].z - sc; d2.z += tz * tz;
                float tw = col[c].w - sc; d2.w += tw * tw;
            }

            int pbase = f4 << 2;
            float dd[4] = {d2.x, d2.y, d2.z, d2.w};
            float rr[4] = {rp[j].x, rp[j].y, rp[j].z, rp[j].w};
            float lmv[4];
#pragma unroll
            for (int i = 0; i < 4; i++) {
                float t = -(dd[i] * invsig);
                float alpha = exp2f(t * LOG2E);
                alpha = fminf(fmaxf(alpha, 0.01f), 0.99f);
                float log_a = fminf(fmaxf(t, L_LO), L_HI);
                int li = j * 4 + i;
                float lsv = ls[li];
                lmv[i] = lsv + log_a;
                lsv += logf(1.0f - alpha);
                ls[li] = lsv;
                if (!last) {
                    float v = rr[i] * expf(lsv);
                    if (v > vl) { vl = v; pl = pbase + i; }   // ascending p
                } else {
                    lm9[li] = lmv[i];
                }
            }
            if (!last) {
                float4 lm4 = make_float4(lmv[0], lmv[1], lmv[2], lmv[3]);
                __stcs(&stage4[(size_t)k * (BP / 4) + b * 4096 + f4], lm4);
            }
        }
    }

    // ---- epilogue: assemble [b,p,11] output, contiguous 44B per pixel ----
#pragma unroll
    for (int j = 0; j < 4; j++) {
        int f4 = base4 + j * THR;
        int pbase = f4 << 2;
        float* op0 = out + ((size_t)b * Pn + pbase) * (Kn + 1);
        float* op1 = op0 + (Kn + 1);
        float* op2 = op1 + (Kn + 1);
        float* op3 = op2 + (Kn + 1);
#pragma unroll
        for (int kk = 0; kk < Kn - 1; kk++) {
            float4 s = __ldcs(&stage4[(size_t)kk * (BP / 4) + b * 4096 + f4]);
            __stcs(op0 + kk, s.x);
            __stcs(op1 + kk, s.y);
            __stcs(op2 + kk, s.z);
            __stcs(op3 + kk, s.w);
        }
        __stcs(op0 + Kn - 1, lm9[j * 4 + 0]); __stcs(op0 + Kn, ls[j * 4 + 0]);
        __stcs(op1 + Kn - 1, lm9[j * 4 + 1]); __stcs(op1 + Kn, ls[j * 4 + 1]);
        __stcs(op2 + Kn - 1, lm9[j * 4 + 2]); __stcs(op2 + Kn, ls[j * 4 + 2]);
        __stcs(op3 + Kn - 1, lm9[j * 4 + 3]); __stcs(op3 + Kn, ls[j * 4 + 3]);
    }
}

// ---------------------------------------------------------------------------
extern "C" void kernel_launch(void* const* d_in, const int* in_sizes, int n_in,
                              void* d_out, int out_size) {
    const float* features  = (const float*)d_in[0];
    const float* rand_pix  = (const float*)d_in[1];
    const float* conv_w    = (const float*)d_in[2];
    const float* conv_b    = (const float*)d_in[3];
    const float* gate      = (const float*)d_in[4];
    const float* log_sigma = (const float*)d_in[5];
    float* out = (float*)d_out;

    (void)in_sizes; (void)n_in; (void)out_size;

    conv_kernel<<<(BP / 4) / 256, 256>>>((const float4*)features,
                                         conv_w, conv_b, gate);
    step_loop_kernel<<<Bn * 4, THR>>>(out, (const float4*)rand_pix, log_sigma);
}